// round 2
// baseline (speedup 1.0000x reference)
#include <cuda_runtime.h>
#include <cstdint>

// ---------------------------------------------------------------------------
// RSSM rollout: H=16 steps, B=2048
//   x = [stoch(1024) | action(10)]  (K=1034)
//   GRU: gx = x@W_ih^T, gh = h@W_hh^T ; r,z = sigmoid ; n = tanh(xn + r*hn)
//   deter = (1-z)*n + z*h
//   prior: h1 = deter@pW1^T -> LayerNorm -> SiLU ; logits = h1@pW2^T
//   sample: argmax(logits + gumbel)  (JAX threefry, partitionable mode)
//   out[t] = [deter(512) | onehot(1024)]
// ---------------------------------------------------------------------------

#define B_       2048
#define DETER_   512
#define SC_      1024           // STOCH*CLASSES
#define ACT_     10
#define H_       16
#define KCAT     1552           // 1024 + 10 + 512 = 1546, padded to mult of 16
#define OUTW     1536

// __device__ scratch (no allocations allowed)
__device__ float g_Wcat[2048 * KCAT];     // virtual rows: [rz(1024) | xn(512) | hn(512)]
__device__ float g_xh[B_ * KCAT];         // [stoch | action | deter | pad]
__device__ float g_deter[B_ * DETER_];
__device__ float g_rz[B_ * 1024];
__device__ float g_xn[B_ * DETER_];
__device__ float g_hn[B_ * DETER_];
__device__ float g_h1raw[B_ * DETER_];
__device__ float g_h1[B_ * DETER_];
__device__ float g_logits[B_ * SC_];

// ---------------------------------------------------------------------------
// Threefry-2x32 (20 rounds), exactly JAX's schedule
// ---------------------------------------------------------------------------
__host__ __device__ __forceinline__ uint32_t rotl32(uint32_t v, int d) {
    return (v << d) | (v >> (32 - d));
}

__host__ __device__ __forceinline__ void threefry2x32(uint32_t k0, uint32_t k1,
                                                      uint32_t x0, uint32_t x1,
                                                      uint32_t& o0, uint32_t& o1) {
    uint32_t ks0 = k0, ks1 = k1, ks2 = k0 ^ k1 ^ 0x1BD11BDAu;
    x0 += ks0; x1 += ks1;
    // 4 rounds (13,15,26,6)
    x0 += x1; x1 = rotl32(x1, 13); x1 ^= x0;
    x0 += x1; x1 = rotl32(x1, 15); x1 ^= x0;
    x0 += x1; x1 = rotl32(x1, 26); x1 ^= x0;
    x0 += x1; x1 = rotl32(x1, 6);  x1 ^= x0;
    x0 += ks1; x1 += ks2 + 1u;
    x0 += x1; x1 = rotl32(x1, 17); x1 ^= x0;
    x0 += x1; x1 = rotl32(x1, 29); x1 ^= x0;
    x0 += x1; x1 = rotl32(x1, 16); x1 ^= x0;
    x0 += x1; x1 = rotl32(x1, 24); x1 ^= x0;
    x0 += ks2; x1 += ks0 + 2u;
    x0 += x1; x1 = rotl32(x1, 13); x1 ^= x0;
    x0 += x1; x1 = rotl32(x1, 15); x1 ^= x0;
    x0 += x1; x1 = rotl32(x1, 26); x1 ^= x0;
    x0 += x1; x1 = rotl32(x1, 6);  x1 ^= x0;
    x0 += ks0; x1 += ks1 + 3u;
    x0 += x1; x1 = rotl32(x1, 17); x1 ^= x0;
    x0 += x1; x1 = rotl32(x1, 29); x1 ^= x0;
    x0 += x1; x1 = rotl32(x1, 16); x1 ^= x0;
    x0 += x1; x1 = rotl32(x1, 24); x1 ^= x0;
    x0 += ks1; x1 += ks2 + 4u;
    x0 += x1; x1 = rotl32(x1, 13); x1 ^= x0;
    x0 += x1; x1 = rotl32(x1, 15); x1 ^= x0;
    x0 += x1; x1 = rotl32(x1, 26); x1 ^= x0;
    x0 += x1; x1 = rotl32(x1, 6);  x1 ^= x0;
    x0 += ks2; x1 += ks0 + 5u;
    o0 = x0; o1 = x1;
}

// ---------------------------------------------------------------------------
// Init / weight prep
// ---------------------------------------------------------------------------
__global__ void init_kernel(const float* __restrict__ stoch0,
                            const float* __restrict__ act_seq,
                            const float* __restrict__ deter0) {
    int gid = blockIdx.x * blockDim.x + threadIdx.x;
    if (gid >= B_ * KCAT) return;
    int b = gid / KCAT, k = gid % KCAT;
    float v = 0.f;
    if (k < SC_)             v = stoch0[b * SC_ + k];
    else if (k < SC_ + ACT_) v = act_seq[b * ACT_ + (k - SC_)];      // t = 0
    else if (k < 1546)       v = deter0[b * DETER_ + (k - SC_ - ACT_)];
    g_xh[gid] = v;
    if (k < DETER_) g_deter[b * DETER_ + k] = deter0[b * DETER_ + k];
}

__global__ void wprep_kernel(const float* __restrict__ W_ih,
                             const float* __restrict__ W_hh) {
    int gid = blockIdx.x * blockDim.x + threadIdx.x;
    if (gid >= 2048 * KCAT) return;
    int r = gid / KCAT, k = gid % KCAT;
    float v = 0.f;
    if (r < 1024) {                       // rz rows: [W_ih row r | W_hh row r]
        if (k < 1034)       v = W_ih[r * 1034 + k];
        else if (k < 1546)  v = W_hh[r * 512 + (k - 1034)];
    } else if (r < 1536) {                // xn rows: W_ih row r (r = 1024+d)
        if (k < 1034)       v = W_ih[r * 1034 + k];
    } else {                              // hn rows: W_hh row (r-512) = 1024+d
        if (k >= 1034 && k < 1546) v = W_hh[(r - 512) * 512 + (k - 1034)];
    }
    g_Wcat[gid] = v;
}

// ---------------------------------------------------------------------------
// 128x128x8 SIMT SGEMM core: C[m,n] = sum_k A[m,k] * W[n,k]
// ---------------------------------------------------------------------------
__device__ __forceinline__ void gemm_core(const float* __restrict__ A, int lda,
                                          const float* __restrict__ W, int ldw,
                                          int klo, int khi, int bm, int bn,
                                          float acc[8][8], float* sA, float* sB) {
    const int tid  = threadIdx.x;
    const int tx   = tid & 15;
    const int ty   = tid >> 4;
    const int lrow = tid >> 1;            // 0..127
    const int lcol = (tid & 1) << 2;      // 0 or 4
    const float* Ap = A + (size_t)(bm + lrow) * lda + lcol;
    const float* Wp = W + (size_t)(bn + lrow) * ldw + lcol;
    for (int k0 = klo; k0 < khi; k0 += 8) {
        float4 av = *(const float4*)(Ap + k0);
        float4 wv = *(const float4*)(Wp + k0);
        __syncthreads();
        sA[(lcol + 0) * 128 + lrow] = av.x;
        sA[(lcol + 1) * 128 + lrow] = av.y;
        sA[(lcol + 2) * 128 + lrow] = av.z;
        sA[(lcol + 3) * 128 + lrow] = av.w;
        sB[(lcol + 0) * 128 + lrow] = wv.x;
        sB[(lcol + 1) * 128 + lrow] = wv.y;
        sB[(lcol + 2) * 128 + lrow] = wv.z;
        sB[(lcol + 3) * 128 + lrow] = wv.w;
        __syncthreads();
#pragma unroll
        for (int kk = 0; kk < 8; kk++) {
            float a[8], b[8];
            *(float4*)(a)     = *(const float4*)(sA + kk * 128 + ty * 8);
            *(float4*)(a + 4) = *(const float4*)(sA + kk * 128 + ty * 8 + 4);
            *(float4*)(b)     = *(const float4*)(sB + kk * 128 + tx * 8);
            *(float4*)(b + 4) = *(const float4*)(sB + kk * 128 + tx * 8 + 4);
#pragma unroll
            for (int i = 0; i < 8; i++)
#pragma unroll
                for (int j = 0; j < 8; j++)
                    acc[i][j] += a[i] * b[j];
        }
    }
}

// GRU GEMM: N = 2048 virtual cols; region-dependent K-range (no wasted MACs)
__global__ void gru_gemm(const float* __restrict__ b_ih,
                         const float* __restrict__ b_hh) {
    __shared__ float sA[8 * 128];
    __shared__ float sB[8 * 128];
    float acc[8][8] = {};
    int bm = blockIdx.y * 128, bn = blockIdx.x * 128;
    int klo, khi;
    if (bn < 1024)      { klo = 0;    khi = KCAT; }   // rz: full K
    else if (bn < 1536) { klo = 0;    khi = 1040; }   // xn: x-part only
    else                { klo = 1032; khi = KCAT; }   // hn: h-part only
    gemm_core(g_xh, KCAT, g_Wcat, KCAT, klo, khi, bm, bn, acc, sA, sB);
    int tx = threadIdx.x & 15, ty = threadIdx.x >> 4;
#pragma unroll
    for (int i = 0; i < 8; i++) {
        int m = bm + ty * 8 + i;
#pragma unroll
        for (int j = 0; j < 8; j++) {
            int n = bn + tx * 8 + j;
            float v = acc[i][j];
            if (n < 1024)       g_rz[m * 1024 + n] = v + b_ih[n] + b_hh[n];
            else if (n < 1536)  g_xn[m * 512 + (n - 1024)] = v + b_ih[n];
            else                g_hn[m * 512 + (n - 1536)] = v + b_hh[(n - 1536) + 1024];
        }
    }
}

__global__ void gemm_b1(const float* __restrict__ pW1, const float* __restrict__ pb1) {
    __shared__ float sA[8 * 128];
    __shared__ float sB[8 * 128];
    float acc[8][8] = {};
    int bm = blockIdx.y * 128, bn = blockIdx.x * 128;
    gemm_core(g_deter, 512, pW1, 512, 0, 512, bm, bn, acc, sA, sB);
    int tx = threadIdx.x & 15, ty = threadIdx.x >> 4;
#pragma unroll
    for (int i = 0; i < 8; i++) {
        int m = bm + ty * 8 + i;
#pragma unroll
        for (int j = 0; j < 8; j++) {
            int n = bn + tx * 8 + j;
            g_h1raw[m * 512 + n] = acc[i][j] + pb1[n];
        }
    }
}

__global__ void gemm_c(const float* __restrict__ pW2, const float* __restrict__ pb2) {
    __shared__ float sA[8 * 128];
    __shared__ float sB[8 * 128];
    float acc[8][8] = {};
    int bm = blockIdx.y * 128, bn = blockIdx.x * 128;
    gemm_core(g_h1, 512, pW2, 512, 0, 512, bm, bn, acc, sA, sB);
    int tx = threadIdx.x & 15, ty = threadIdx.x >> 4;
#pragma unroll
    for (int i = 0; i < 8; i++) {
        int m = bm + ty * 8 + i;
#pragma unroll
        for (int j = 0; j < 8; j++) {
            int n = bn + tx * 8 + j;
            g_logits[m * 1024 + n] = acc[i][j] + pb2[n];
        }
    }
}

// ---------------------------------------------------------------------------
// GRU gates + deter update; writes out[t][b][0:512]
// ---------------------------------------------------------------------------
__global__ void gates_kernel(float* __restrict__ out, int t) {
    int gid = blockIdx.x * blockDim.x + threadIdx.x;   // 2048*512 threads
    int b = gid >> 9, d = gid & 511;
    float sr = g_rz[b * 1024 + d];
    float sz = g_rz[b * 1024 + 512 + d];
    float xn = g_xn[b * 512 + d];
    float hn = g_hn[b * 512 + d];
    float h  = g_xh[b * KCAT + 1034 + d];
    float r = 1.f / (1.f + expf(-sr));
    float z = 1.f / (1.f + expf(-sz));
    float n = tanhf(xn + r * hn);
    float dn = (1.f - z) * n + z * h;
    g_xh[b * KCAT + 1034 + d] = dn;
    g_deter[b * 512 + d] = dn;
    out[((size_t)t * B_ + b) * OUTW + d] = dn;
}

// ---------------------------------------------------------------------------
// LayerNorm + SiLU over rows of g_h1raw
// ---------------------------------------------------------------------------
__global__ void ln_kernel(const float* __restrict__ pg, const float* __restrict__ pbeta) {
    __shared__ float red[256];
    int b = blockIdx.x, tid = threadIdx.x;
    const float* x = g_h1raw + b * 512;
    float v0 = x[tid], v1 = x[tid + 256];
    red[tid] = v0 + v1;
    __syncthreads();
    for (int s = 128; s > 0; s >>= 1) {
        if (tid < s) red[tid] += red[tid + s];
        __syncthreads();
    }
    float mean = red[0] * (1.f / 512.f);
    __syncthreads();
    float d0 = v0 - mean, d1 = v1 - mean;
    red[tid] = d0 * d0 + d1 * d1;
    __syncthreads();
    for (int s = 128; s > 0; s >>= 1) {
        if (tid < s) red[tid] += red[tid + s];
        __syncthreads();
    }
    float var = red[0] * (1.f / 512.f);
    float rstd = rsqrtf(var + 1e-5f);
    float y0 = d0 * rstd * pg[tid] + pbeta[tid];
    float y1 = d1 * rstd * pg[tid + 256] + pbeta[tid + 256];
    g_h1[b * 512 + tid]       = y0 * (1.f / (1.f + expf(-y0)));
    g_h1[b * 512 + tid + 256] = y1 * (1.f / (1.f + expf(-y1)));
}

// ---------------------------------------------------------------------------
// Gumbel-max sampling (JAX partitionable threefry), writes onehot to
// out[t][b][512:1536] and next-step stoch; also stages next-step action.
// ---------------------------------------------------------------------------
__global__ void sample_kernel(const float* __restrict__ act_seq,
                              float* __restrict__ out,
                              int t, uint32_t k0, uint32_t k1) {
    int gid = blockIdx.x * blockDim.x + threadIdx.x;   // 2048*32 threads
    int b = gid >> 5, s = gid & 31;
    const float* lg = g_logits + b * 1024 + s * 32;
    float best = -1e30f;
    int bi = 0;
#pragma unroll 4
    for (int c = 0; c < 32; c++) {
        uint32_t idx = (uint32_t)(b * 1024 + s * 32 + c);
        uint32_t o0, o1;
        threefry2x32(k0, k1, 0u, idx, o0, o1);
        uint32_t bits = o0 ^ o1;
        float u = __uint_as_float((bits >> 9) | 0x3f800000u) - 1.0f;
        u = fmaxf(u, 1.1754943508222875e-38f);
        float g = -logf(-logf(u));
        float v = g + lg[c];
        if (v > best) { best = v; bi = c; }
    }
    float* xs = g_xh + b * KCAT + s * 32;
    float* os = out + ((size_t)t * B_ + b) * OUTW + 512 + s * 32;
#pragma unroll
    for (int c = 0; c < 32; c++) {
        float v = (c == bi) ? 1.0f : 0.0f;
        xs[c] = v;
        os[c] = v;
    }
    if (t < H_ - 1 && s < ACT_) {
        g_xh[b * KCAT + SC_ + s] = act_seq[(((size_t)(t + 1)) * B_ + b) * ACT_ + s];
    }
}

// ---------------------------------------------------------------------------
// Host launcher
// ---------------------------------------------------------------------------
extern "C" void kernel_launch(void* const* d_in, const int* in_sizes, int n_in,
                              void* d_out, int out_size) {
    const float* act    = (const float*)d_in[0];
    const float* deter0 = (const float*)d_in[1];
    const float* stoch0 = (const float*)d_in[2];
    const float* W_ih   = (const float*)d_in[3];
    const float* b_ih   = (const float*)d_in[4];
    const float* W_hh   = (const float*)d_in[5];
    const float* b_hh   = (const float*)d_in[6];
    const float* pW1    = (const float*)d_in[7];
    const float* pb1    = (const float*)d_in[8];
    const float* pg     = (const float*)d_in[9];
    const float* pbeta  = (const float*)d_in[10];
    const float* pW2    = (const float*)d_in[11];
    const float* pb2    = (const float*)d_in[12];
    float* out = (float*)d_out;

    // Per-step keys: split(key(42), 16) under threefry_partitionable (fold-like):
    // key_t = threefry2x32((0,42), (0,t))
    uint32_t keys[H_][2];
    for (int t = 0; t < H_; t++) {
        uint32_t o0, o1;
        threefry2x32(0u, 42u, 0u, (uint32_t)t, o0, o1);
        keys[t][0] = o0;
        keys[t][1] = o1;
    }

    cudaStream_t st = cudaStreamPerThread;
    int nfill = B_ * KCAT;
    init_kernel<<<(nfill + 255) / 256, 256, 0, st>>>(stoch0, act, deter0);
    wprep_kernel<<<(2048 * KCAT + 255) / 256, 256, 0, st>>>(W_ih, W_hh);

    for (int t = 0; t < H_; t++) {
        gru_gemm<<<dim3(16, 16), 256, 0, st>>>(b_ih, b_hh);
        gates_kernel<<<(B_ * DETER_) / 256, 256, 0, st>>>(out, t);
        gemm_b1<<<dim3(4, 16), 256, 0, st>>>(pW1, pb1);
        ln_kernel<<<B_, 256, 0, st>>>(pg, pbeta);
        gemm_c<<<dim3(8, 16), 256, 0, st>>>(pW2, pb2);
        sample_kernel<<<(B_ * 32) / 128, 128, 0, st>>>(act, out, t, keys[t][0], keys[t][1]);
    }
}